// round 14
// baseline (speedup 1.0000x reference)
#include <cuda_runtime.h>
#include <cstdint>

// Problem constants
#define BB 4
#define SS 1024
#define HH 1024
#define NHH 16
#define HDD 64
#define BH (BB*NHH)          // 64
#define CTX_ELEMS (BB*SS*HH)                 // 4,194,304
#define SCORES_ELEMS (BH*SS*SS)              // 67,108,864

// Scratch (static device memory — allocation-free rule)
__device__ float g_q[BH*SS*HDD];
__device__ float g_k[BH*SS*HDD];
__device__ float g_v[BH*SS*HDD];
__device__ float g_scores_fb[SCORES_ELEMS];
__device__ float g_ctx_fb[CTX_ELEMS];

// ===========================================================================
// mma.sync tf32 helpers (baseline PTX; tcgen05 rejected by sm_103 target)
// ===========================================================================
__device__ __forceinline__ uint32_t f2tf(float f) {
    uint32_t r;
    asm("cvt.rna.tf32.f32 %0, %1;" : "=r"(r) : "f"(f));
    return r;
}
__device__ __forceinline__ void mma_tf32(float* c,
    uint32_t a0, uint32_t a1, uint32_t a2, uint32_t a3,
    uint32_t b0, uint32_t b1)
{
    asm volatile(
        "mma.sync.aligned.m16n8k8.row.col.f32.tf32.tf32.f32 "
        "{%0,%1,%2,%3}, {%4,%5,%6,%7}, {%8,%9}, {%0,%1,%2,%3};"
        : "+f"(c[0]), "+f"(c[1]), "+f"(c[2]), "+f"(c[3])
        : "r"(a0), "r"(a1), "r"(a2), "r"(a3), "r"(b0), "r"(b1));
}

#define TSTR 136   // [k][m] tile stride: conflict-free fragment LDS
#define VSTR 72    // V tile [t][d] stride
#define PBUF (32*TSTR)
#define MMA_SMEM_BYTES (4*PBUF*4)    // 69,632 B

// fused kernel smem layout (words), t-tile = 128
#define FQ_OFF  0
#define FK_OFF  (64*TSTR)                 // 8704
#define FP_OFF  (FK_OFF + 64*TSTR)        // 17408
#define FV_OFF  (FP_OFF + 128*TSTR)       // 34816
#define FR_OFF  (FV_OFF + 128*VSTR)       // 44032
#define FUSED_SMEM_BYTES ((FR_OFF + 128) * 4)   // 176,640 B

// ---------------------------------------------------------------------------
// Kernel 1: projection via mma.sync tf32, 512 threads (16 warps).
// Same 128x128x32 tiling / double-buffered smem as the round-4 kernel;
// warp grid 4x4 (warp tile 32m x 32n), per-thread state halved.
// ---------------------------------------------------------------------------
__global__ __launch_bounds__(512) void proj_mma_kernel(
    const float* __restrict__ X, const float* __restrict__ W,
    const float* __restrict__ bias, float* __restrict__ out)
{
    extern __shared__ uint32_t sm[];
    uint32_t* As = sm;
    uint32_t* Bs = sm + 2*PBUF;

    const int tid  = threadIdx.x;
    const int warp = tid >> 5, lane = tid & 31;
    const int wm = warp & 3, wn = warp >> 2;   // 32m x 32n per warp
    const int n0 = blockIdx.x * 128, m0 = blockIdx.y * 128;
    const int lrow = tid >> 2;                 // 0..127
    const int cq   = (tid & 3) * 8;            // k offset 0/8/16/24

    const float* Xr = X + (size_t)(m0 + lrow) * 1024 + cq;
    const float* Wr = W + (size_t)(n0 + lrow) * 1024 + cq;

    float c[2][4][4];
#pragma unroll
    for (int mt = 0; mt < 2; mt++)
#pragma unroll
        for (int nt = 0; nt < 4; nt++)
#pragma unroll
            for (int e = 0; e < 4; e++) c[mt][nt][e] = 0.f;

    const int r  = lane >> 2;
    const int ci = lane & 3;

    float4 pa[2], pb[2];
#pragma unroll
    for (int j = 0; j < 2; j++) {
        pa[j] = *(const float4*)(Xr + 4 * j);
        pb[j] = *(const float4*)(Wr + 4 * j);
    }
    {
        uint32_t* da = As;
        uint32_t* db = Bs;
#pragma unroll
        for (int j = 0; j < 2; j++) {
            int k = cq + 4 * j;
            da[(k+0)*TSTR + lrow] = f2tf(pa[j].x);
            da[(k+1)*TSTR + lrow] = f2tf(pa[j].y);
            da[(k+2)*TSTR + lrow] = f2tf(pa[j].z);
            da[(k+3)*TSTR + lrow] = f2tf(pa[j].w);
            db[(k+0)*TSTR + lrow] = f2tf(pb[j].x);
            db[(k+1)*TSTR + lrow] = f2tf(pb[j].y);
            db[(k+2)*TSTR + lrow] = f2tf(pb[j].z);
            db[(k+3)*TSTR + lrow] = f2tf(pb[j].w);
        }
    }
    __syncthreads();

    for (int i = 0; i < 32; i++) {
        if (i + 1 < 32) {
            const float* xr = Xr + (i + 1) * 32;
            const float* wr = Wr + (i + 1) * 32;
#pragma unroll
            for (int j = 0; j < 2; j++) {
                pa[j] = *(const float4*)(xr + 4 * j);
                pb[j] = *(const float4*)(wr + 4 * j);
            }
        }
        {
            uint32_t* Ab = As + (i & 1) * PBUF + wm * 32;
            uint32_t* Bb = Bs + (i & 1) * PBUF + wn * 32;
#pragma unroll
            for (int kf = 0; kf < 32; kf += 8) {
                uint32_t a[2][4], b[4][2];
#pragma unroll
                for (int mt = 0; mt < 2; mt++) {
                    a[mt][0] = Ab[(kf+ci  )*TSTR + mt*16 + r];
                    a[mt][1] = Ab[(kf+ci  )*TSTR + mt*16 + r + 8];
                    a[mt][2] = Ab[(kf+4+ci)*TSTR + mt*16 + r];
                    a[mt][3] = Ab[(kf+4+ci)*TSTR + mt*16 + r + 8];
                }
#pragma unroll
                for (int nt = 0; nt < 4; nt++) {
                    b[nt][0] = Bb[(kf+ci  )*TSTR + nt*8 + r];
                    b[nt][1] = Bb[(kf+4+ci)*TSTR + nt*8 + r];
                }
#pragma unroll
                for (int mt = 0; mt < 2; mt++)
#pragma unroll
                    for (int nt = 0; nt < 4; nt++)
                        mma_tf32(c[mt][nt], a[mt][0], a[mt][1], a[mt][2], a[mt][3],
                                 b[nt][0], b[nt][1]);
            }
        }
        if (i + 1 < 32) {
            uint32_t* da = As + ((i + 1) & 1) * PBUF;
            uint32_t* db = Bs + ((i + 1) & 1) * PBUF;
#pragma unroll
            for (int j = 0; j < 2; j++) {
                int k = cq + 4 * j;
                da[(k+0)*TSTR + lrow] = f2tf(pa[j].x);
                da[(k+1)*TSTR + lrow] = f2tf(pa[j].y);
                da[(k+2)*TSTR + lrow] = f2tf(pa[j].z);
                da[(k+3)*TSTR + lrow] = f2tf(pa[j].w);
                db[(k+0)*TSTR + lrow] = f2tf(pb[j].x);
                db[(k+1)*TSTR + lrow] = f2tf(pb[j].y);
                db[(k+2)*TSTR + lrow] = f2tf(pb[j].z);
                db[(k+3)*TSTR + lrow] = f2tf(pb[j].w);
            }
            __syncthreads();
        }
    }

    const int nb   = n0 + wn * 32;
    const int head = nb >> 6;
    const int d0   = nb & 63;
#pragma unroll
    for (int mt = 0; mt < 2; mt++) {
        int m = m0 + wm * 32 + mt * 16 + r;
        int bidx = m >> 10, s = m & 1023;
        float* po = out + (((size_t)(bidx * NHH + head)) * SS + s) * HDD + d0;
#pragma unroll
        for (int nt = 0; nt < 4; nt++) {
            int dn = nt * 8 + ci * 2;
            float2 bb = *(const float2*)&bias[nb + dn];
            float2 o0, o1;
            o0.x = c[mt][nt][0] + bb.x;  o0.y = c[mt][nt][1] + bb.y;
            o1.x = c[mt][nt][2] + bb.x;  o1.y = c[mt][nt][3] + bb.y;
            *(float2*)&po[dn]          = o0;
            *(float2*)&po[dn + 8*HDD]  = o1;
        }
    }
}

// ---------------------------------------------------------------------------
// Kernel 2 (fused): scores + softmax (no max-sub) + P@V, t-tile = 128,
// 512 threads (16 warps) — round-13 best (308us), unchanged.
// ---------------------------------------------------------------------------
__global__ __launch_bounds__(512) void fused_attn_kernel(
    const float* __restrict__ Q, const float* __restrict__ K,
    const float* __restrict__ V, const int* __restrict__ mask,
    float* __restrict__ scores, float* __restrict__ ctx)
{
    extern __shared__ uint32_t sm[];
    uint32_t* Qs = sm + FQ_OFF;    // [64 d][TSTR] tf32
    uint32_t* Ks = sm + FK_OFF;    // [64 d][TSTR]
    uint32_t* Ps = sm + FP_OFF;    // [128 t][TSTR] tf32 exp values
    uint32_t* Vs = sm + FV_OFF;    // [128 t][VSTR]
    float*    Rs = (float*)(sm + FR_OFF);   // [128] row sums

    const int tid  = threadIdx.x;
    const int warp = tid >> 5, lane = tid & 31;
    const int r  = lane >> 2;
    const int ci = lane & 3;
    const int bh = blockIdx.y;
    const int s0 = blockIdx.x * 128;

    const float* Qb = Q + (size_t)bh * SS * HDD;
    const float* Kb = K + (size_t)bh * SS * HDD;
    const float* Vb = V + (size_t)bh * SS * HDD;

    const int lrow = tid >> 2;          // 0..127
    const int cq   = (tid & 3) * 16;    // d quarter

    if (tid < 128) Rs[tid] = 0.f;

    // load Q tile (once): Qs[d][s], 4 float4 per thread
    {
        const float* qr = Qb + (size_t)(s0 + lrow) * HDD + cq;
#pragma unroll
        for (int j = 0; j < 4; j++) {
            float4 v = *(const float4*)(qr + 4 * j);
            int k = cq + 4 * j;
            Qs[(k+0)*TSTR + lrow] = f2tf(v.x);
            Qs[(k+1)*TSTR + lrow] = f2tf(v.y);
            Qs[(k+2)*TSTR + lrow] = f2tf(v.z);
            Qs[(k+3)*TSTR + lrow] = f2tf(v.w);
        }
    }

    const int wm = warp & 3, wn = warp >> 2;   // S: 32s x 32t | PV: 32s x 16d

    float o[2][2][4];
#pragma unroll
    for (int mt = 0; mt < 2; mt++)
#pragma unroll
        for (int nt = 0; nt < 2; nt++)
#pragma unroll
            for (int e = 0; e < 4; e++) o[mt][nt][e] = 0.f;

    for (int tt = 0; tt < 8; tt++) {
        const int t0 = tt * 128;
        __syncthreads();   // Ks/Vs/Ps reuse barrier (also orders Rs zeroing)
        // load K,V tiles (rows t0..t0+127), 4 float4 each per thread
        {
            const float* kr = Kb + (size_t)(t0 + lrow) * HDD + cq;
            const float* vr = Vb + (size_t)(t0 + lrow) * HDD + cq;
#pragma unroll
            for (int j = 0; j < 4; j++) {
                float4 kv = *(const float4*)(kr + 4 * j);
                float4 vv = *(const float4*)(vr + 4 * j);
                int k = cq + 4 * j;
                Ks[(k+0)*TSTR + lrow] = f2tf(kv.x);
                Ks[(k+1)*TSTR + lrow] = f2tf(kv.y);
                Ks[(k+2)*TSTR + lrow] = f2tf(kv.z);
                Ks[(k+3)*TSTR + lrow] = f2tf(kv.w);
                Vs[lrow*VSTR + k+0] = f2tf(vv.x);
                Vs[lrow*VSTR + k+1] = f2tf(vv.y);
                Vs[lrow*VSTR + k+2] = f2tf(vv.z);
                Vs[lrow*VSTR + k+3] = f2tf(vv.w);
            }
        }
        __syncthreads();

        // ---- prefetch mask tile into registers (consumed after S-MMA) ----
        int2 mk0[2][4], mk1[2][4];
#pragma unroll
        for (int mt = 0; mt < 2; mt++) {
            int s = wm * 32 + mt * 16 + r;
            size_t rowoff = ((size_t)bh * SS + (s0 + s)) * SS;
#pragma unroll
            for (int nt = 0; nt < 4; nt++) {
                int lt = wn * 32 + nt * 8 + ci * 2;
                size_t off0 = rowoff + t0 + lt;
                mk0[mt][nt] = *(const int2*)&mask[off0];
                mk1[mt][nt] = *(const int2*)&mask[off0 + 8 * SS];
            }
        }

        // ---- S = Q K^T for this tile (warp: 32s x 32t) ----
        float c[2][4][4];
#pragma unroll
        for (int mt = 0; mt < 2; mt++)
#pragma unroll
            for (int nt = 0; nt < 4; nt++)
#pragma unroll
                for (int e = 0; e < 4; e++) c[mt][nt][e] = 0.f;

        uint32_t* Ab = Qs + wm * 32;
        uint32_t* Bb = Ks + wn * 32;
#pragma unroll
        for (int kf = 0; kf < 64; kf += 8) {
            uint32_t a[2][4], b[4][2];
#pragma unroll
            for (int mt = 0; mt < 2; mt++) {
                a[mt][0] = Ab[(kf+ci  )*TSTR + mt*16 + r];
                a[mt][1] = Ab[(kf+ci  )*TSTR + mt*16 + r + 8];
                a[mt][2] = Ab[(kf+4+ci)*TSTR + mt*16 + r];
                a[mt][3] = Ab[(kf+4+ci)*TSTR + mt*16 + r + 8];
            }
#pragma unroll
            for (int nt = 0; nt < 4; nt++) {
                b[nt][0] = Bb[(kf+ci  )*TSTR + nt*8 + r];
                b[nt][1] = Bb[(kf+4+ci)*TSTR + nt*8 + r];
            }
#pragma unroll
            for (int mt = 0; mt < 2; mt++)
#pragma unroll
                for (int nt = 0; nt < 4; nt++)
                    mma_tf32(c[mt][nt], a[mt][0], a[mt][1], a[mt][2], a[mt][3],
                             b[nt][0], b[nt][1]);
        }

        // ---- epilogue: mask+scale, write scores, exp -> Ps, rowsum ----
#pragma unroll
        for (int mt = 0; mt < 2; mt++) {
            int s = wm * 32 + mt * 16 + r;
            size_t rowoff = ((size_t)bh * SS + (s0 + s)) * SS;
            float rsa = 0.f, rsb = 0.f;   // rows s and s+8
#pragma unroll
            for (int nt = 0; nt < 4; nt++) {
                int lt = wn * 32 + nt * 8 + ci * 2;
                size_t off0 = rowoff + t0 + lt;
                size_t off1 = off0 + 8 * SS;
                float2 sv0, sv1;
                sv0.x = c[mt][nt][0] * 0.125f + (mk0[mt][nt].x != 0 ? -9999.f : 0.f);
                sv0.y = c[mt][nt][1] * 0.125f + (mk0[mt][nt].y != 0 ? -9999.f : 0.f);
                sv1.x = c[mt][nt][2] * 0.125f + (mk1[mt][nt].x != 0 ? -9999.f : 0.f);
                sv1.y = c[mt][nt][3] * 0.125f + (mk1[mt][nt].y != 0 ? -9999.f : 0.f);
                *(float2*)&scores[off0] = sv0;
                *(float2*)&scores[off1] = sv1;
                uint32_t p0 = f2tf(__expf(sv0.x));
                uint32_t p1 = f2tf(__expf(sv0.y));
                uint32_t p2 = f2tf(__expf(sv1.x));
                uint32_t p3 = f2tf(__expf(sv1.y));
                Ps[(lt  )*TSTR + s    ] = p0;
                Ps[(lt+1)*TSTR + s    ] = p1;
                Ps[(lt  )*TSTR + s + 8] = p2;
                Ps[(lt+1)*TSTR + s + 8] = p3;
                rsa += __uint_as_float(p0) + __uint_as_float(p1);
                rsb += __uint_as_float(p2) + __uint_as_float(p3);
            }
            rsa += __shfl_xor_sync(0xffffffffu, rsa, 1);
            rsa += __shfl_xor_sync(0xffffffffu, rsa, 2);
            rsb += __shfl_xor_sync(0xffffffffu, rsb, 1);
            rsb += __shfl_xor_sync(0xffffffffu, rsb, 2);
            if (ci == 0) {
                atomicAdd(&Rs[s], rsa);
                atomicAdd(&Rs[s + 8], rsb);
            }
        }
        __syncthreads();   // Ps visible

        // ---- PV accumulate: o += P(128s x 128t) @ V(128t x 64d) ----
        {
            uint32_t* Pb = Ps + wm * 32;
            uint32_t* Vbk = Vs + wn * 16;
#pragma unroll
            for (int kf = 0; kf < 128; kf += 8) {
                uint32_t a[2][4], b[2][2];
#pragma unroll
                for (int mt = 0; mt < 2; mt++) {
                    a[mt][0] = Pb[(kf+ci  )*TSTR + mt*16 + r];
                    a[mt][1] = Pb[(kf+ci  )*TSTR + mt*16 + r + 8];
                    a[mt][2] = Pb[(kf+4+ci)*TSTR + mt*16 + r];
                    a[mt][3] = Pb[(kf+4+ci)*TSTR + mt*16 + r + 8];
                }
#pragma unroll
                for (int nt = 0; nt < 2; nt++) {
                    b[nt][0] = Vbk[(kf+ci  )*VSTR + nt*8 + r];
                    b[nt][1] = Vbk[(kf+4+ci)*VSTR + nt*8 + r];
                }
#pragma unroll
                for (int mt = 0; mt < 2; mt++)
#pragma unroll
                    for (int nt = 0; nt < 2; nt++)
                        mma_tf32(o[mt][nt], a[mt][0], a[mt][1], a[mt][2], a[mt][3],
                                 b[nt][0], b[nt][1]);
            }
        }
    }

    __syncthreads();

    // final: normalize, write ctx [b][s][h*64+d]
    const int bidx = bh >> 4;
    const int h = bh & 15;
#pragma unroll
    for (int mt = 0; mt < 2; mt++) {
        int s = wm * 32 + mt * 16 + r;
        float inv0 = 1.f / Rs[s];
        float inv1 = 1.f / Rs[s + 8];
        float* po0 = ctx + ((size_t)bidx * SS + (s0 + s)) * HH + h * HDD;
        float* po1 = po0 + 8 * HH;
#pragma unroll
        for (int nt = 0; nt < 2; nt++) {
            int d = wn * 16 + nt * 8 + ci * 2;
            float2 w0, w1;
            w0.x = o[mt][nt][0] * inv0;  w0.y = o[mt][nt][1] * inv0;
            w1.x = o[mt][nt][2] * inv1;  w1.y = o[mt][nt][3] * inv1;
            *(float2*)&po0[d] = w0;
            *(float2*)&po1[d] = w1;
        }
    }
}

// ---------------------------------------------------------------------------
extern "C" void kernel_launch(void* const* d_in, const int* in_sizes, int n_in,
                              void* d_out, int out_size) {
    const float* qx = (const float*)d_in[0];
    const float* kx = (const float*)d_in[1];
    const float* vx = (const float*)d_in[2];
    const int* mask = (const int*)d_in[3];
    const float* Wq = (const float*)d_in[4];
    const float* bq = (const float*)d_in[5];
    const float* Wk = (const float*)d_in[6];
    const float* bk = (const float*)d_in[7];
    const float* Wv = (const float*)d_in[8];
    const float* bv = (const float*)d_in[9];

    float *qp, *kp, *vp, *sfb, *cfb;
    cudaGetSymbolAddress((void**)&qp, g_q);
    cudaGetSymbolAddress((void**)&kp, g_k);
    cudaGetSymbolAddress((void**)&vp, g_v);
    cudaGetSymbolAddress((void**)&sfb, g_scores_fb);
    cudaGetSymbolAddress((void**)&cfb, g_ctx_fb);

    float* ctx_out;
    float* scores_out;
    if (out_size >= CTX_ELEMS + SCORES_ELEMS) {
        ctx_out = (float*)d_out;
        scores_out = (float*)d_out + CTX_ELEMS;
    } else if (out_size == SCORES_ELEMS) {
        scores_out = (float*)d_out;
        ctx_out = cfb;
    } else {
        ctx_out = (float*)d_out;
        scores_out = sfb;
    }

    cudaFuncSetAttribute(proj_mma_kernel,
                         cudaFuncAttributeMaxDynamicSharedMemorySize, MMA_SMEM_BYTES);
    cudaFuncSetAttribute(fused_attn_kernel,
                         cudaFuncAttributeMaxDynamicSharedMemorySize, FUSED_SMEM_BYTES);

    dim3 pg(8, 32);  // N/128, M/128
    proj_mma_kernel<<<pg, 512, MMA_SMEM_BYTES>>>(qx, Wq, bq, qp);
    proj_mma_kernel<<<pg, 512, MMA_SMEM_BYTES>>>(kx, Wk, bk, kp);
    proj_mma_kernel<<<pg, 512, MMA_SMEM_BYTES>>>(vx, Wv, bv, vp);
    fused_attn_kernel<<<dim3(8, BH), 512, FUSED_SMEM_BYTES>>>(
        qp, kp, vp, mask, scores_out, ctx_out);
}

// round 15
// speedup vs baseline: 1.1021x; 1.1021x over previous
#include <cuda_runtime.h>
#include <cstdint>

// Problem constants
#define BB 4
#define SS 1024
#define HH 1024
#define NHH 16
#define HDD 64
#define BH (BB*NHH)          // 64
#define CTX_ELEMS (BB*SS*HH)                 // 4,194,304
#define SCORES_ELEMS (BH*SS*SS)              // 67,108,864

// Scratch (static device memory — allocation-free rule)
__device__ float g_q[BH*SS*HDD];
__device__ float g_k[BH*SS*HDD];
__device__ float g_v[BH*SS*HDD];
__device__ float g_scores_fb[SCORES_ELEMS];
__device__ float g_ctx_fb[CTX_ELEMS];

// ===========================================================================
// mma.sync tf32 helpers (baseline PTX; tcgen05 rejected by sm_103 target)
// ===========================================================================
__device__ __forceinline__ uint32_t f2tf(float f) {
    uint32_t r;
    asm("cvt.rna.tf32.f32 %0, %1;" : "=r"(r) : "f"(f));
    return r;
}
__device__ __forceinline__ void mma_tf32(float* c,
    uint32_t a0, uint32_t a1, uint32_t a2, uint32_t a3,
    uint32_t b0, uint32_t b1)
{
    asm volatile(
        "mma.sync.aligned.m16n8k8.row.col.f32.tf32.tf32.f32 "
        "{%0,%1,%2,%3}, {%4,%5,%6,%7}, {%8,%9}, {%0,%1,%2,%3};"
        : "+f"(c[0]), "+f"(c[1]), "+f"(c[2]), "+f"(c[3])
        : "r"(a0), "r"(a1), "r"(a2), "r"(a3), "r"(b0), "r"(b1));
}

#define TSTR 136   // [k][m] tile stride: conflict-free fragment LDS
#define VSTR 72    // V tile [t][d] stride
#define PBUF (32*TSTR)
#define MMA_SMEM_BYTES (4*PBUF*4)    // 69,632 B

// fused kernel smem layout (words), t-tile = 128
#define FQ_OFF  0
#define FK_OFF  (64*TSTR)                 // 8704
#define FP_OFF  (FK_OFF + 64*TSTR)        // 17408
#define FV_OFF  (FP_OFF + 128*TSTR)       // 34816
#define FR_OFF  (FV_OFF + 128*VSTR)       // 44032
#define FUSED_SMEM_BYTES ((FR_OFF + 128) * 4)   // 176,640 B

// ---------------------------------------------------------------------------
// Kernel 1: projection via mma.sync tf32 (round-4 geometry, 256 threads)
// + pair-interleaved A smem layout: rows (m, m+8) adjacent -> A-fragment
// loads become LDS.64, halving the critical-path LDS count.
// pidx(m) = (m>>4)*16 + (m&7)*2 + ((m>>3)&1)
// ---------------------------------------------------------------------------
__global__ __launch_bounds__(256) void proj_mma_kernel(
    const float* __restrict__ X, const float* __restrict__ W,
    const float* __restrict__ bias, float* __restrict__ out)
{
    extern __shared__ uint32_t sm[];
    uint32_t* As = sm;
    uint32_t* Bs = sm + 2*PBUF;

    const int tid  = threadIdx.x;
    const int warp = tid >> 5, lane = tid & 31;
    const int wm = warp & 1, wn = warp >> 1;
    const int n0 = blockIdx.x * 128, m0 = blockIdx.y * 128;
    const int lrow = tid >> 1;
    const int cq   = (tid & 1) * 16;
    // pair-interleaved index for A rows
    const int pidx = ((lrow >> 4) << 4) + ((lrow & 7) << 1) + ((lrow >> 3) & 1);

    const float* Xr = X + (size_t)(m0 + lrow) * 1024 + cq;
    const float* Wr = W + (size_t)(n0 + lrow) * 1024 + cq;

    float c[4][4][4];
#pragma unroll
    for (int mt = 0; mt < 4; mt++)
#pragma unroll
        for (int nt = 0; nt < 4; nt++)
#pragma unroll
            for (int e = 0; e < 4; e++) c[mt][nt][e] = 0.f;

    const int r  = lane >> 2;
    const int ci = lane & 3;

    float4 pa[4], pb[4];
#pragma unroll
    for (int j = 0; j < 4; j++) {
        pa[j] = *(const float4*)(Xr + 4 * j);
        pb[j] = *(const float4*)(Wr + 4 * j);
    }
    {
        uint32_t* da = As;
        uint32_t* db = Bs;
#pragma unroll
        for (int j = 0; j < 4; j++) {
            int k = cq + 4 * j;
            da[(k+0)*TSTR + pidx] = f2tf(pa[j].x);
            da[(k+1)*TSTR + pidx] = f2tf(pa[j].y);
            da[(k+2)*TSTR + pidx] = f2tf(pa[j].z);
            da[(k+3)*TSTR + pidx] = f2tf(pa[j].w);
            db[(k+0)*TSTR + lrow] = f2tf(pb[j].x);
            db[(k+1)*TSTR + lrow] = f2tf(pb[j].y);
            db[(k+2)*TSTR + lrow] = f2tf(pb[j].z);
            db[(k+3)*TSTR + lrow] = f2tf(pb[j].w);
        }
    }
    __syncthreads();

    for (int i = 0; i < 32; i++) {
        if (i + 1 < 32) {
            const float* xr = Xr + (i + 1) * 32;
            const float* wr = Wr + (i + 1) * 32;
#pragma unroll
            for (int j = 0; j < 4; j++) {
                pa[j] = *(const float4*)(xr + 4 * j);
                pb[j] = *(const float4*)(wr + 4 * j);
            }
        }
        {
            uint32_t* Ab = As + (i & 1) * PBUF + wm * 64;
            uint32_t* Bb = Bs + (i & 1) * PBUF + wn * 32;
#pragma unroll
            for (int kf = 0; kf < 32; kf += 8) {
                uint32_t a[4][4], b[4][2];
#pragma unroll
                for (int mt = 0; mt < 4; mt++) {
                    uint2 va0 = *(const uint2*)&Ab[(kf+ci  )*TSTR + mt*16 + r*2];
                    uint2 va1 = *(const uint2*)&Ab[(kf+4+ci)*TSTR + mt*16 + r*2];
                    a[mt][0] = va0.x;  a[mt][1] = va0.y;
                    a[mt][2] = va1.x;  a[mt][3] = va1.y;
                }
#pragma unroll
                for (int nt = 0; nt < 4; nt++) {
                    b[nt][0] = Bb[(kf+ci  )*TSTR + nt*8 + r];
                    b[nt][1] = Bb[(kf+4+ci)*TSTR + nt*8 + r];
                }
#pragma unroll
                for (int mt = 0; mt < 4; mt++)
#pragma unroll
                    for (int nt = 0; nt < 4; nt++)
                        mma_tf32(c[mt][nt], a[mt][0], a[mt][1], a[mt][2], a[mt][3],
                                 b[nt][0], b[nt][1]);
            }
        }
        if (i + 1 < 32) {
            uint32_t* da = As + ((i + 1) & 1) * PBUF;
            uint32_t* db = Bs + ((i + 1) & 1) * PBUF;
#pragma unroll
            for (int j = 0; j < 4; j++) {
                int k = cq + 4 * j;
                da[(k+0)*TSTR + pidx] = f2tf(pa[j].x);
                da[(k+1)*TSTR + pidx] = f2tf(pa[j].y);
                da[(k+2)*TSTR + pidx] = f2tf(pa[j].z);
                da[(k+3)*TSTR + pidx] = f2tf(pa[j].w);
                db[(k+0)*TSTR + lrow] = f2tf(pb[j].x);
                db[(k+1)*TSTR + lrow] = f2tf(pb[j].y);
                db[(k+2)*TSTR + lrow] = f2tf(pb[j].z);
                db[(k+3)*TSTR + lrow] = f2tf(pb[j].w);
            }
            __syncthreads();
        }
    }

    const int nb   = n0 + wn * 32;
    const int head = nb >> 6;
    const int d0   = nb & 63;
#pragma unroll
    for (int mt = 0; mt < 4; mt++) {
        int m = m0 + wm * 64 + mt * 16 + r;
        int bidx = m >> 10, s = m & 1023;
        float* po = out + (((size_t)(bidx * NHH + head)) * SS + s) * HDD + d0;
#pragma unroll
        for (int nt = 0; nt < 4; nt++) {
            int dn = nt * 8 + ci * 2;
            float2 bb = *(const float2*)&bias[nb + dn];
            float2 o0, o1;
            o0.x = c[mt][nt][0] + bb.x;  o0.y = c[mt][nt][1] + bb.y;
            o1.x = c[mt][nt][2] + bb.x;  o1.y = c[mt][nt][3] + bb.y;
            *(float2*)&po[dn]          = o0;
            *(float2*)&po[dn + 8*HDD]  = o1;
        }
    }
}

// ---------------------------------------------------------------------------
// Kernel 2 (fused): scores + softmax (no max-sub) + P@V, t-tile = 128,
// 512 threads (16 warps) — round-13 best (308us), unchanged.
// ---------------------------------------------------------------------------
__global__ __launch_bounds__(512) void fused_attn_kernel(
    const float* __restrict__ Q, const float* __restrict__ K,
    const float* __restrict__ V, const int* __restrict__ mask,
    float* __restrict__ scores, float* __restrict__ ctx)
{
    extern __shared__ uint32_t sm[];
    uint32_t* Qs = sm + FQ_OFF;    // [64 d][TSTR] tf32
    uint32_t* Ks = sm + FK_OFF;    // [64 d][TSTR]
    uint32_t* Ps = sm + FP_OFF;    // [128 t][TSTR] tf32 exp values
    uint32_t* Vs = sm + FV_OFF;    // [128 t][VSTR]
    float*    Rs = (float*)(sm + FR_OFF);   // [128] row sums

    const int tid  = threadIdx.x;
    const int warp = tid >> 5, lane = tid & 31;
    const int r  = lane >> 2;
    const int ci = lane & 3;
    const int bh = blockIdx.y;
    const int s0 = blockIdx.x * 128;

    const float* Qb = Q + (size_t)bh * SS * HDD;
    const float* Kb = K + (size_t)bh * SS * HDD;
    const float* Vb = V + (size_t)bh * SS * HDD;

    const int lrow = tid >> 2;          // 0..127
    const int cq   = (tid & 3) * 16;    // d quarter

    if (tid < 128) Rs[tid] = 0.f;

    // load Q tile (once): Qs[d][s], 4 float4 per thread
    {
        const float* qr = Qb + (size_t)(s0 + lrow) * HDD + cq;
#pragma unroll
        for (int j = 0; j < 4; j++) {
            float4 v = *(const float4*)(qr + 4 * j);
            int k = cq + 4 * j;
            Qs[(k+0)*TSTR + lrow] = f2tf(v.x);
            Qs[(k+1)*TSTR + lrow] = f2tf(v.y);
            Qs[(k+2)*TSTR + lrow] = f2tf(v.z);
            Qs[(k+3)*TSTR + lrow] = f2tf(v.w);
        }
    }

    const int wm = warp & 3, wn = warp >> 2;   // S: 32s x 32t | PV: 32s x 16d

    float o[2][2][4];
#pragma unroll
    for (int mt = 0; mt < 2; mt++)
#pragma unroll
        for (int nt = 0; nt < 2; nt++)
#pragma unroll
            for (int e = 0; e < 4; e++) o[mt][nt][e] = 0.f;

    for (int tt = 0; tt < 8; tt++) {
        const int t0 = tt * 128;
        __syncthreads();   // Ks/Vs/Ps reuse barrier (also orders Rs zeroing)
        // load K,V tiles (rows t0..t0+127), 4 float4 each per thread
        {
            const float* kr = Kb + (size_t)(t0 + lrow) * HDD + cq;
            const float* vr = Vb + (size_t)(t0 + lrow) * HDD + cq;
#pragma unroll
            for (int j = 0; j < 4; j++) {
                float4 kv = *(const float4*)(kr + 4 * j);
                float4 vv = *(const float4*)(vr + 4 * j);
                int k = cq + 4 * j;
                Ks[(k+0)*TSTR + lrow] = f2tf(kv.x);
                Ks[(k+1)*TSTR + lrow] = f2tf(kv.y);
                Ks[(k+2)*TSTR + lrow] = f2tf(kv.z);
                Ks[(k+3)*TSTR + lrow] = f2tf(kv.w);
                Vs[lrow*VSTR + k+0] = f2tf(vv.x);
                Vs[lrow*VSTR + k+1] = f2tf(vv.y);
                Vs[lrow*VSTR + k+2] = f2tf(vv.z);
                Vs[lrow*VSTR + k+3] = f2tf(vv.w);
            }
        }
        __syncthreads();

        // ---- prefetch mask tile into registers (consumed after S-MMA) ----
        int2 mk0[2][4], mk1[2][4];
#pragma unroll
        for (int mt = 0; mt < 2; mt++) {
            int s = wm * 32 + mt * 16 + r;
            size_t rowoff = ((size_t)bh * SS + (s0 + s)) * SS;
#pragma unroll
            for (int nt = 0; nt < 4; nt++) {
                int lt = wn * 32 + nt * 8 + ci * 2;
                size_t off0 = rowoff + t0 + lt;
                mk0[mt][nt] = *(const int2*)&mask[off0];
                mk1[mt][nt] = *(const int2*)&mask[off0 + 8 * SS];
            }
        }

        // ---- S = Q K^T for this tile (warp: 32s x 32t) ----
        float c[2][4][4];
#pragma unroll
        for (int mt = 0; mt < 2; mt++)
#pragma unroll
            for (int nt = 0; nt < 4; nt++)
#pragma unroll
                for (int e = 0; e < 4; e++) c[mt][nt][e] = 0.f;

        uint32_t* Ab = Qs + wm * 32;
        uint32_t* Bb = Ks + wn * 32;
#pragma unroll
        for (int kf = 0; kf < 64; kf += 8) {
            uint32_t a[2][4], b[4][2];
#pragma unroll
            for (int mt = 0; mt < 2; mt++) {
                a[mt][0] = Ab[(kf+ci  )*TSTR + mt*16 + r];
                a[mt][1] = Ab[(kf+ci  )*TSTR + mt*16 + r + 8];
                a[mt][2] = Ab[(kf+4+ci)*TSTR + mt*16 + r];
                a[mt][3] = Ab[(kf+4+ci)*TSTR + mt*16 + r + 8];
            }
#pragma unroll
            for (int nt = 0; nt < 4; nt++) {
                b[nt][0] = Bb[(kf+ci  )*TSTR + nt*8 + r];
                b[nt][1] = Bb[(kf+4+ci)*TSTR + nt*8 + r];
            }
#pragma unroll
            for (int mt = 0; mt < 2; mt++)
#pragma unroll
                for (int nt = 0; nt < 4; nt++)
                    mma_tf32(c[mt][nt], a[mt][0], a[mt][1], a[mt][2], a[mt][3],
                             b[nt][0], b[nt][1]);
        }

        // ---- epilogue: mask+scale, write scores, exp -> Ps, rowsum ----
#pragma unroll
        for (int mt = 0; mt < 2; mt++) {
            int s = wm * 32 + mt * 16 + r;
            size_t rowoff = ((size_t)bh * SS + (s0 + s)) * SS;
            float rsa = 0.f, rsb = 0.f;   // rows s and s+8
#pragma unroll
            for (int nt = 0; nt < 4; nt++) {
                int lt = wn * 32 + nt * 8 + ci * 2;
                size_t off0 = rowoff + t0 + lt;
                size_t off1 = off0 + 8 * SS;
                float2 sv0, sv1;
                sv0.x = c[mt][nt][0] * 0.125f + (mk0[mt][nt].x != 0 ? -9999.f : 0.f);
                sv0.y = c[mt][nt][1] * 0.125f + (mk0[mt][nt].y != 0 ? -9999.f : 0.f);
                sv1.x = c[mt][nt][2] * 0.125f + (mk1[mt][nt].x != 0 ? -9999.f : 0.f);
                sv1.y = c[mt][nt][3] * 0.125f + (mk1[mt][nt].y != 0 ? -9999.f : 0.f);
                *(float2*)&scores[off0] = sv0;
                *(float2*)&scores[off1] = sv1;
                uint32_t p0 = f2tf(__expf(sv0.x));
                uint32_t p1 = f2tf(__expf(sv0.y));
                uint32_t p2 = f2tf(__expf(sv1.x));
                uint32_t p3 = f2tf(__expf(sv1.y));
                Ps[(lt  )*TSTR + s    ] = p0;
                Ps[(lt+1)*TSTR + s    ] = p1;
                Ps[(lt  )*TSTR + s + 8] = p2;
                Ps[(lt+1)*TSTR + s + 8] = p3;
                rsa += __uint_as_float(p0) + __uint_as_float(p1);
                rsb += __uint_as_float(p2) + __uint_as_float(p3);
            }
            rsa += __shfl_xor_sync(0xffffffffu, rsa, 1);
            rsa += __shfl_xor_sync(0xffffffffu, rsa, 2);
            rsb += __shfl_xor_sync(0xffffffffu, rsb, 1);
            rsb += __shfl_xor_sync(0xffffffffu, rsb, 2);
            if (ci == 0) {
                atomicAdd(&Rs[s], rsa);
                atomicAdd(&Rs[s + 8], rsb);
            }
        }
        __syncthreads();   // Ps visible

        // ---- PV accumulate: o += P(128s x 128t) @ V(128t x 64d) ----
        {
            uint32_t* Pb = Ps + wm * 32;
            uint32_t* Vbk = Vs + wn * 16;
#pragma unroll
            for (int kf = 0; kf < 128; kf += 8) {
                uint32_t a[2][4], b[2][2];
#pragma unroll
                for (int mt = 0; mt < 2; mt++) {
                    a[mt][0] = Pb[(kf+ci  )*TSTR + mt*16 + r];
                    a[mt][1] = Pb[(kf+ci  )*TSTR + mt*16 + r + 8];
                    a[mt][2] = Pb[(kf+4+ci)*TSTR + mt*16 + r];
                    a[mt][3] = Pb[(kf+4+ci)*TSTR + mt*16 + r + 8];
                }
#pragma unroll
                for (int nt = 0; nt < 2; nt++) {
                    b[nt][0] = Vbk[(kf+ci  )*VSTR + nt*8 + r];
                    b[nt][1] = Vbk[(kf+4+ci)*VSTR + nt*8 + r];
                }
#pragma unroll
                for (int mt = 0; mt < 2; mt++)
#pragma unroll
                    for (int nt = 0; nt < 2; nt++)
                        mma_tf32(o[mt][nt], a[mt][0], a[mt][1], a[mt][2], a[mt][3],
                                 b[nt][0], b[nt][1]);
            }
        }
    }

    __syncthreads();

    // final: normalize, write ctx [b][s][h*64+d]
    const int bidx = bh >> 4;
    const int h = bh & 15;
#pragma unroll
    for (int mt = 0; mt < 2; mt++) {
        int s = wm * 32 + mt * 16 + r;
        float inv0 = 1.f / Rs[s];
        float inv1 = 1.f / Rs[s + 8];
        float* po0 = ctx + ((size_t)bidx * SS + (s0 + s)) * HH + h * HDD;
        float* po1 = po0 + 8 * HH;
#pragma unroll
        for (int nt = 0; nt < 2; nt++) {
            int d = wn * 16 + nt * 8 + ci * 2;
            float2 w0, w1;
            w0.x = o[mt][nt][0] * inv0;  w0.y = o[mt][nt][1] * inv0;
            w1.x = o[mt][nt][2] * inv1;  w1.y = o[mt][nt][3] * inv1;
            *(float2*)&po0[d] = w0;
            *(float2*)&po1[d] = w1;
        }
    }
}

// ---------------------------------------------------------------------------
extern "C" void kernel_launch(void* const* d_in, const int* in_sizes, int n_in,
                              void* d_out, int out_size) {
    const float* qx = (const float*)d_in[0];
    const float* kx = (const float*)d_in[1];
    const float* vx = (const float*)d_in[2];
    const int* mask = (const int*)d_in[3];
    const float* Wq = (const float*)d_in[4];
    const float* bq = (const float*)d_in[5];
    const float* Wk = (const float*)d_in[6];
    const float* bk = (const float*)d_in[7];
    const float* Wv = (const float*)d_in[8];
    const float* bv = (const float*)d_in[9];

    float *qp, *kp, *vp, *sfb, *cfb;
    cudaGetSymbolAddress((void**)&qp, g_q);
    cudaGetSymbolAddress((void**)&kp, g_k);
    cudaGetSymbolAddress((void**)&vp, g_v);
    cudaGetSymbolAddress((void**)&sfb, g_scores_fb);
    cudaGetSymbolAddress((void**)&cfb, g_ctx_fb);

    float* ctx_out;
    float* scores_out;
    if (out_size >= CTX_ELEMS + SCORES_ELEMS) {
        ctx_out = (float*)d_out;
        scores_out = (float*)d_out + CTX_ELEMS;
    } else if (out_size == SCORES_ELEMS) {
        scores_out = (float*)d_out;
        ctx_out = cfb;
    } else {
        ctx_out = (float*)d_out;
        scores_out = sfb;
    }

    cudaFuncSetAttribute(proj_mma_kernel,
                         cudaFuncAttributeMaxDynamicSharedMemorySize, MMA_SMEM_BYTES);
    cudaFuncSetAttribute(fused_attn_kernel,
                         cudaFuncAttributeMaxDynamicSharedMemorySize, FUSED_SMEM_BYTES);

    dim3 pg(8, 32);  // N/128, M/128
    proj_mma_kernel<<<pg, 256, MMA_SMEM_BYTES>>>(qx, Wq, bq, qp);
    proj_mma_kernel<<<pg, 256, MMA_SMEM_BYTES>>>(kx, Wk, bk, kp);
    proj_mma_kernel<<<pg, 256, MMA_SMEM_BYTES>>>(vx, Wv, bv, vp);
    fused_attn_kernel<<<dim3(8, BH), 512, FUSED_SMEM_BYTES>>>(
        qp, kp, vp, mask, scores_out, ctx_out);
}

// round 16
// speedup vs baseline: 1.1216x; 1.0177x over previous
#include <cuda_runtime.h>
#include <cstdint>

// Problem constants
#define BB 4
#define SS 1024
#define HH 1024
#define NHH 16
#define HDD 64
#define BH (BB*NHH)          // 64
#define CTX_ELEMS (BB*SS*HH)                 // 4,194,304
#define SCORES_ELEMS (BH*SS*SS)              // 67,108,864

// Scratch (static device memory — allocation-free rule)
__device__ float g_q[BH*SS*HDD];
__device__ float g_k[BH*SS*HDD];
__device__ float g_v[BH*SS*HDD];
__device__ float g_scores_fb[SCORES_ELEMS];
__device__ float g_ctx_fb[CTX_ELEMS];

// ===========================================================================
// mma.sync tf32 helpers (baseline PTX; tcgen05 rejected by sm_103 target)
// ===========================================================================
__device__ __forceinline__ uint32_t f2tf(float f) {
    uint32_t r;
    asm("cvt.rna.tf32.f32 %0, %1;" : "=r"(r) : "f"(f));
    return r;
}
__device__ __forceinline__ void mma_tf32(float* c,
    uint32_t a0, uint32_t a1, uint32_t a2, uint32_t a3,
    uint32_t b0, uint32_t b1)
{
    asm volatile(
        "mma.sync.aligned.m16n8k8.row.col.f32.tf32.tf32.f32 "
        "{%0,%1,%2,%3}, {%4,%5,%6,%7}, {%8,%9}, {%0,%1,%2,%3};"
        : "+f"(c[0]), "+f"(c[1]), "+f"(c[2]), "+f"(c[3])
        : "r"(a0), "r"(a1), "r"(a2), "r"(a3), "r"(b0), "r"(b1));
}

// pair-interleave: rows (m, m+8) adjacent within each 16-row block
__device__ __forceinline__ int pair_idx(int m) {
    return ((m >> 4) << 4) + ((m & 7) << 1) + ((m >> 3) & 1);
}

#define TSTR 136   // [k][m] tile stride: conflict-free fragment LDS
#define VSTR 72    // V tile [t][d] stride
#define PBUF (32*TSTR)
#define MMA_SMEM_BYTES (4*PBUF*4)    // 69,632 B

// fused kernel smem layout (words), t-tile = 128
#define FQ_OFF  0
#define FK_OFF  (64*TSTR)                 // 8704
#define FP_OFF  (FK_OFF + 64*TSTR)        // 17408
#define FV_OFF  (FP_OFF + 128*TSTR)       // 34816
#define FR_OFF  (FV_OFF + 128*VSTR)       // 44032
#define FUSED_SMEM_BYTES ((FR_OFF + 128) * 4)   // 176,640 B

// ---------------------------------------------------------------------------
// Kernel 1: projection via mma.sync tf32 (round-15: pair-interleaved A,
// LDS.64 A-fragments; 256 threads) — unchanged.
// ---------------------------------------------------------------------------
__global__ __launch_bounds__(256) void proj_mma_kernel(
    const float* __restrict__ X, const float* __restrict__ W,
    const float* __restrict__ bias, float* __restrict__ out)
{
    extern __shared__ uint32_t sm[];
    uint32_t* As = sm;
    uint32_t* Bs = sm + 2*PBUF;

    const int tid  = threadIdx.x;
    const int warp = tid >> 5, lane = tid & 31;
    const int wm = warp & 1, wn = warp >> 1;
    const int n0 = blockIdx.x * 128, m0 = blockIdx.y * 128;
    const int lrow = tid >> 1;
    const int cq   = (tid & 1) * 16;
    const int pidx = pair_idx(lrow);

    const float* Xr = X + (size_t)(m0 + lrow) * 1024 + cq;
    const float* Wr = W + (size_t)(n0 + lrow) * 1024 + cq;

    float c[4][4][4];
#pragma unroll
    for (int mt = 0; mt < 4; mt++)
#pragma unroll
        for (int nt = 0; nt < 4; nt++)
#pragma unroll
            for (int e = 0; e < 4; e++) c[mt][nt][e] = 0.f;

    const int r  = lane >> 2;
    const int ci = lane & 3;

    float4 pa[4], pb[4];
#pragma unroll
    for (int j = 0; j < 4; j++) {
        pa[j] = *(const float4*)(Xr + 4 * j);
        pb[j] = *(const float4*)(Wr + 4 * j);
    }
    {
        uint32_t* da = As;
        uint32_t* db = Bs;
#pragma unroll
        for (int j = 0; j < 4; j++) {
            int k = cq + 4 * j;
            da[(k+0)*TSTR + pidx] = f2tf(pa[j].x);
            da[(k+1)*TSTR + pidx] = f2tf(pa[j].y);
            da[(k+2)*TSTR + pidx] = f2tf(pa[j].z);
            da[(k+3)*TSTR + pidx] = f2tf(pa[j].w);
            db[(k+0)*TSTR + lrow] = f2tf(pb[j].x);
            db[(k+1)*TSTR + lrow] = f2tf(pb[j].y);
            db[(k+2)*TSTR + lrow] = f2tf(pb[j].z);
            db[(k+3)*TSTR + lrow] = f2tf(pb[j].w);
        }
    }
    __syncthreads();

    for (int i = 0; i < 32; i++) {
        if (i + 1 < 32) {
            const float* xr = Xr + (i + 1) * 32;
            const float* wr = Wr + (i + 1) * 32;
#pragma unroll
            for (int j = 0; j < 4; j++) {
                pa[j] = *(const float4*)(xr + 4 * j);
                pb[j] = *(const float4*)(wr + 4 * j);
            }
        }
        {
            uint32_t* Ab = As + (i & 1) * PBUF + wm * 64;
            uint32_t* Bb = Bs + (i & 1) * PBUF + wn * 32;
#pragma unroll
            for (int kf = 0; kf < 32; kf += 8) {
                uint32_t a[4][4], b[4][2];
#pragma unroll
                for (int mt = 0; mt < 4; mt++) {
                    uint2 va0 = *(const uint2*)&Ab[(kf+ci  )*TSTR + mt*16 + r*2];
                    uint2 va1 = *(const uint2*)&Ab[(kf+4+ci)*TSTR + mt*16 + r*2];
                    a[mt][0] = va0.x;  a[mt][1] = va0.y;
                    a[mt][2] = va1.x;  a[mt][3] = va1.y;
                }
#pragma unroll
                for (int nt = 0; nt < 4; nt++) {
                    b[nt][0] = Bb[(kf+ci  )*TSTR + nt*8 + r];
                    b[nt][1] = Bb[(kf+4+ci)*TSTR + nt*8 + r];
                }
#pragma unroll
                for (int mt = 0; mt < 4; mt++)
#pragma unroll
                    for (int nt = 0; nt < 4; nt++)
                        mma_tf32(c[mt][nt], a[mt][0], a[mt][1], a[mt][2], a[mt][3],
                                 b[nt][0], b[nt][1]);
            }
        }
        if (i + 1 < 32) {
            uint32_t* da = As + ((i + 1) & 1) * PBUF;
            uint32_t* db = Bs + ((i + 1) & 1) * PBUF;
#pragma unroll
            for (int j = 0; j < 4; j++) {
                int k = cq + 4 * j;
                da[(k+0)*TSTR + pidx] = f2tf(pa[j].x);
                da[(k+1)*TSTR + pidx] = f2tf(pa[j].y);
                da[(k+2)*TSTR + pidx] = f2tf(pa[j].z);
                da[(k+3)*TSTR + pidx] = f2tf(pa[j].w);
                db[(k+0)*TSTR + lrow] = f2tf(pb[j].x);
                db[(k+1)*TSTR + lrow] = f2tf(pb[j].y);
                db[(k+2)*TSTR + lrow] = f2tf(pb[j].z);
                db[(k+3)*TSTR + lrow] = f2tf(pb[j].w);
            }
            __syncthreads();
        }
    }

    const int nb   = n0 + wn * 32;
    const int head = nb >> 6;
    const int d0   = nb & 63;
#pragma unroll
    for (int mt = 0; mt < 4; mt++) {
        int m = m0 + wm * 64 + mt * 16 + r;
        int bidx = m >> 10, s = m & 1023;
        float* po = out + (((size_t)(bidx * NHH + head)) * SS + s) * HDD + d0;
#pragma unroll
        for (int nt = 0; nt < 4; nt++) {
            int dn = nt * 8 + ci * 2;
            float2 bb = *(const float2*)&bias[nb + dn];
            float2 o0, o1;
            o0.x = c[mt][nt][0] + bb.x;  o0.y = c[mt][nt][1] + bb.y;
            o1.x = c[mt][nt][2] + bb.x;  o1.y = c[mt][nt][3] + bb.y;
            *(float2*)&po[dn]          = o0;
            *(float2*)&po[dn + 8*HDD]  = o1;
        }
    }
}

// ---------------------------------------------------------------------------
// Kernel 2 (fused): scores + softmax (no max-sub) + P@V, t-tile = 128,
// 512 threads. Round-13 structure + pair-interleaved s-dimension in Qs/Ps:
// A-fragment loads become LDS.64 (S and PV loops), epilogue Ps stores
// become STS.64 pairs.
// ---------------------------------------------------------------------------
__global__ __launch_bounds__(512) void fused_attn_kernel(
    const float* __restrict__ Q, const float* __restrict__ K,
    const float* __restrict__ V, const int* __restrict__ mask,
    float* __restrict__ scores, float* __restrict__ ctx)
{
    extern __shared__ uint32_t sm[];
    uint32_t* Qs = sm + FQ_OFF;    // [64 d][TSTR] tf32, s pair-interleaved
    uint32_t* Ks = sm + FK_OFF;    // [64 d][TSTR]
    uint32_t* Ps = sm + FP_OFF;    // [128 t][TSTR] exp tf32, s pair-interleaved
    uint32_t* Vs = sm + FV_OFF;    // [128 t][VSTR]
    float*    Rs = (float*)(sm + FR_OFF);   // [128] row sums

    const int tid  = threadIdx.x;
    const int warp = tid >> 5, lane = tid & 31;
    const int r  = lane >> 2;
    const int ci = lane & 3;
    const int bh = blockIdx.y;
    const int s0 = blockIdx.x * 128;

    const float* Qb = Q + (size_t)bh * SS * HDD;
    const float* Kb = K + (size_t)bh * SS * HDD;
    const float* Vb = V + (size_t)bh * SS * HDD;

    const int lrow = tid >> 2;          // 0..127
    const int cq   = (tid & 3) * 16;    // d quarter
    const int plrow = pair_idx(lrow);   // pair-interleaved s index

    if (tid < 128) Rs[tid] = 0.f;

    // load Q tile (once): Qs[d][pidx(s)], 4 float4 per thread
    {
        const float* qr = Qb + (size_t)(s0 + lrow) * HDD + cq;
#pragma unroll
        for (int j = 0; j < 4; j++) {
            float4 v = *(const float4*)(qr + 4 * j);
            int k = cq + 4 * j;
            Qs[(k+0)*TSTR + plrow] = f2tf(v.x);
            Qs[(k+1)*TSTR + plrow] = f2tf(v.y);
            Qs[(k+2)*TSTR + plrow] = f2tf(v.z);
            Qs[(k+3)*TSTR + plrow] = f2tf(v.w);
        }
    }

    const int wm = warp & 3, wn = warp >> 2;   // S: 32s x 32t | PV: 32s x 16d

    float o[2][2][4];
#pragma unroll
    for (int mt = 0; mt < 2; mt++)
#pragma unroll
        for (int nt = 0; nt < 2; nt++)
#pragma unroll
            for (int e = 0; e < 4; e++) o[mt][nt][e] = 0.f;

    for (int tt = 0; tt < 8; tt++) {
        const int t0 = tt * 128;
        __syncthreads();   // Ks/Vs/Ps reuse barrier (also orders Rs zeroing)
        // load K,V tiles (rows t0..t0+127), 4 float4 each per thread
        {
            const float* kr = Kb + (size_t)(t0 + lrow) * HDD + cq;
            const float* vr = Vb + (size_t)(t0 + lrow) * HDD + cq;
#pragma unroll
            for (int j = 0; j < 4; j++) {
                float4 kv = *(const float4*)(kr + 4 * j);
                float4 vv = *(const float4*)(vr + 4 * j);
                int k = cq + 4 * j;
                Ks[(k+0)*TSTR + lrow] = f2tf(kv.x);
                Ks[(k+1)*TSTR + lrow] = f2tf(kv.y);
                Ks[(k+2)*TSTR + lrow] = f2tf(kv.z);
                Ks[(k+3)*TSTR + lrow] = f2tf(kv.w);
                Vs[lrow*VSTR + k+0] = f2tf(vv.x);
                Vs[lrow*VSTR + k+1] = f2tf(vv.y);
                Vs[lrow*VSTR + k+2] = f2tf(vv.z);
                Vs[lrow*VSTR + k+3] = f2tf(vv.w);
            }
        }
        __syncthreads();

        // ---- prefetch mask tile into registers (consumed after S-MMA) ----
        int2 mk0[2][4], mk1[2][4];
#pragma unroll
        for (int mt = 0; mt < 2; mt++) {
            int s = wm * 32 + mt * 16 + r;
            size_t rowoff = ((size_t)bh * SS + (s0 + s)) * SS;
#pragma unroll
            for (int nt = 0; nt < 4; nt++) {
                int lt = wn * 32 + nt * 8 + ci * 2;
                size_t off0 = rowoff + t0 + lt;
                mk0[mt][nt] = *(const int2*)&mask[off0];
                mk1[mt][nt] = *(const int2*)&mask[off0 + 8 * SS];
            }
        }

        // ---- S = Q K^T for this tile (warp: 32s x 32t), LDS.64 A-frags ----
        float c[2][4][4];
#pragma unroll
        for (int mt = 0; mt < 2; mt++)
#pragma unroll
            for (int nt = 0; nt < 4; nt++)
#pragma unroll
                for (int e = 0; e < 4; e++) c[mt][nt][e] = 0.f;

        uint32_t* Ab = Qs + wm * 32;
        uint32_t* Bb = Ks + wn * 32;
#pragma unroll
        for (int kf = 0; kf < 64; kf += 8) {
            uint32_t a[2][4], b[4][2];
#pragma unroll
            for (int mt = 0; mt < 2; mt++) {
                uint2 va0 = *(const uint2*)&Ab[(kf+ci  )*TSTR + mt*16 + r*2];
                uint2 va1 = *(const uint2*)&Ab[(kf+4+ci)*TSTR + mt*16 + r*2];
                a[mt][0] = va0.x;  a[mt][1] = va0.y;
                a[mt][2] = va1.x;  a[mt][3] = va1.y;
            }
#pragma unroll
            for (int nt = 0; nt < 4; nt++) {
                b[nt][0] = Bb[(kf+ci  )*TSTR + nt*8 + r];
                b[nt][1] = Bb[(kf+4+ci)*TSTR + nt*8 + r];
            }
#pragma unroll
            for (int mt = 0; mt < 2; mt++)
#pragma unroll
                for (int nt = 0; nt < 4; nt++)
                    mma_tf32(c[mt][nt], a[mt][0], a[mt][1], a[mt][2], a[mt][3],
                             b[nt][0], b[nt][1]);
        }

        // ---- epilogue: mask+scale, write scores, exp -> Ps (STS.64) ----
#pragma unroll
        for (int mt = 0; mt < 2; mt++) {
            int s = wm * 32 + mt * 16 + r;
            int pbase = ((s >> 4) << 4) + r * 2;   // pidx(s); pidx(s+8)=pbase+1
            size_t rowoff = ((size_t)bh * SS + (s0 + s)) * SS;
            float rsa = 0.f, rsb = 0.f;   // rows s and s+8
#pragma unroll
            for (int nt = 0; nt < 4; nt++) {
                int lt = wn * 32 + nt * 8 + ci * 2;
                size_t off0 = rowoff + t0 + lt;
                size_t off1 = off0 + 8 * SS;
                float2 sv0, sv1;
                sv0.x = c[mt][nt][0] * 0.125f + (mk0[mt][nt].x != 0 ? -9999.f : 0.f);
                sv0.y = c[mt][nt][1] * 0.125f + (mk0[mt][nt].y != 0 ? -9999.f : 0.f);
                sv1.x = c[mt][nt][2] * 0.125f + (mk1[mt][nt].x != 0 ? -9999.f : 0.f);
                sv1.y = c[mt][nt][3] * 0.125f + (mk1[mt][nt].y != 0 ? -9999.f : 0.f);
                *(float2*)&scores[off0] = sv0;
                *(float2*)&scores[off1] = sv1;
                uint32_t p0 = f2tf(__expf(sv0.x));
                uint32_t p1 = f2tf(__expf(sv0.y));
                uint32_t p2 = f2tf(__expf(sv1.x));
                uint32_t p3 = f2tf(__expf(sv1.y));
                uint2 w02 = make_uint2(p0, p2);   // rows (s, s+8) at col lt
                uint2 w13 = make_uint2(p1, p3);   // rows (s, s+8) at col lt+1
                *(uint2*)&Ps[(lt  )*TSTR + pbase] = w02;
                *(uint2*)&Ps[(lt+1)*TSTR + pbase] = w13;
                rsa += __uint_as_float(p0) + __uint_as_float(p1);
                rsb += __uint_as_float(p2) + __uint_as_float(p3);
            }
            rsa += __shfl_xor_sync(0xffffffffu, rsa, 1);
            rsa += __shfl_xor_sync(0xffffffffu, rsa, 2);
            rsb += __shfl_xor_sync(0xffffffffu, rsb, 1);
            rsb += __shfl_xor_sync(0xffffffffu, rsb, 2);
            if (ci == 0) {
                atomicAdd(&Rs[s], rsa);
                atomicAdd(&Rs[s + 8], rsb);
            }
        }
        __syncthreads();   // Ps visible

        // ---- PV accumulate (LDS.64 A-frags): o += P @ V ----
        {
            uint32_t* Pb = Ps + wm * 32;
            uint32_t* Vbk = Vs + wn * 16;
#pragma unroll
            for (int kf = 0; kf < 128; kf += 8) {
                uint32_t a[2][4], b[2][2];
#pragma unroll
                for (int mt = 0; mt < 2; mt++) {
                    uint2 va0 = *(const uint2*)&Pb[(kf+ci  )*TSTR + mt*16 + r*2];
                    uint2 va1 = *(const uint2*)&Pb[(kf+4+ci)*TSTR + mt*16 + r*2];
                    a[mt][0] = va0.x;  a[mt][1] = va0.y;
                    a[mt][2] = va1.x;  a[mt][3] = va1.y;
                }
#pragma unroll
                for (int nt = 0; nt < 2; nt++) {
                    b[nt][0] = Vbk[(kf+ci  )*VSTR + nt*8 + r];
                    b[nt][1] = Vbk[(kf+4+ci)*VSTR + nt*8 + r];
                }
#pragma unroll
                for (int mt = 0; mt < 2; mt++)
#pragma unroll
                    for (int nt = 0; nt < 2; nt++)
                        mma_tf32(o[mt][nt], a[mt][0], a[mt][1], a[mt][2], a[mt][3],
                                 b[nt][0], b[nt][1]);
            }
        }
    }

    __syncthreads();

    // final: normalize, write ctx [b][s][h*64+d]
    const int bidx = bh >> 4;
    const int h = bh & 15;
#pragma unroll
    for (int mt = 0; mt < 2; mt++) {
        int s = wm * 32 + mt * 16 + r;
        float inv0 = 1.f / Rs[s];
        float inv1 = 1.f / Rs[s + 8];
        float* po0 = ctx + ((size_t)bidx * SS + (s0 + s)) * HH + h * HDD;
        float* po1 = po0 + 8 * HH;
#pragma unroll
        for (int nt = 0; nt < 2; nt++) {
            int d = wn * 16 + nt * 8 + ci * 2;
            float2 w0, w1;
            w0.x = o[mt][nt][0] * inv0;  w0.y = o[mt][nt][1] * inv0;
            w1.x = o[mt][nt][2] * inv1;  w1.y = o[mt][nt][3] * inv1;
            *(float2*)&po0[d] = w0;
            *(float2*)&po1[d] = w1;
        }
    }
}

// ---------------------------------------------------------------------------
extern "C" void kernel_launch(void* const* d_in, const int* in_sizes, int n_in,
                              void* d_out, int out_size) {
    const float* qx = (const float*)d_in[0];
    const float* kx = (const float*)d_in[1];
    const float* vx = (const float*)d_in[2];
    const int* mask = (const int*)d_in[3];
    const float* Wq = (const float*)d_in[4];
    const float* bq = (const float*)d_in[5];
    const float* Wk = (const float*)d_in[6];
    const float* bk = (const float*)d_in[7];
    const float* Wv = (const float*)d_in[8];
    const float* bv = (const float*)d_in[9];

    float *qp, *kp, *vp, *sfb, *cfb;
    cudaGetSymbolAddress((void**)&qp, g_q);
    cudaGetSymbolAddress((void**)&kp, g_k);
    cudaGetSymbolAddress((void**)&vp, g_v);
    cudaGetSymbolAddress((void**)&sfb, g_scores_fb);
    cudaGetSymbolAddress((void**)&cfb, g_ctx_fb);

    float* ctx_out;
    float* scores_out;
    if (out_size >= CTX_ELEMS + SCORES_ELEMS) {
        ctx_out = (float*)d_out;
        scores_out = (float*)d_out + CTX_ELEMS;
    } else if (out_size == SCORES_ELEMS) {
        scores_out = (float*)d_out;
        ctx_out = cfb;
    } else {
        ctx_out = (float*)d_out;
        scores_out = sfb;
    }

    cudaFuncSetAttribute(proj_mma_kernel,
                         cudaFuncAttributeMaxDynamicSharedMemorySize, MMA_SMEM_BYTES);
    cudaFuncSetAttribute(fused_attn_kernel,
                         cudaFuncAttributeMaxDynamicSharedMemorySize, FUSED_SMEM_BYTES);

    dim3 pg(8, 32);  // N/128, M/128
    proj_mma_kernel<<<pg, 256, MMA_SMEM_BYTES>>>(qx, Wq, bq, qp);
    proj_mma_kernel<<<pg, 256, MMA_SMEM_BYTES>>>(kx, Wk, bk, kp);
    proj_mma_kernel<<<pg, 256, MMA_SMEM_BYTES>>>(vx, Wv, bv, vp);
    fused_attn_kernel<<<dim3(8, BH), 512, FUSED_SMEM_BYTES>>>(
        qp, kp, vp, mask, scores_out, ctx_out);
}

// round 17
// speedup vs baseline: 1.1365x; 1.0132x over previous
#include <cuda_runtime.h>
#include <cstdint>

// Problem constants
#define BB 4
#define SS 1024
#define HH 1024
#define NHH 16
#define HDD 64
#define BH (BB*NHH)          // 64
#define CTX_ELEMS (BB*SS*HH)                 // 4,194,304
#define SCORES_ELEMS (BH*SS*SS)              // 67,108,864

// Scratch (static device memory — allocation-free rule)
__device__ float g_q[BH*SS*HDD];
__device__ float g_k[BH*SS*HDD];
__device__ float g_v[BH*SS*HDD];
__device__ float g_scores_fb[SCORES_ELEMS];
__device__ float g_ctx_fb[CTX_ELEMS];

// ===========================================================================
// mma.sync tf32 helpers (baseline PTX; tcgen05 rejected by sm_103 target)
// ===========================================================================
__device__ __forceinline__ uint32_t f2tf(float f) {
    uint32_t r;
    asm("cvt.rna.tf32.f32 %0, %1;" : "=r"(r) : "f"(f));
    return r;
}
__device__ __forceinline__ void mma_tf32(float* c,
    uint32_t a0, uint32_t a1, uint32_t a2, uint32_t a3,
    uint32_t b0, uint32_t b1)
{
    asm volatile(
        "mma.sync.aligned.m16n8k8.row.col.f32.tf32.tf32.f32 "
        "{%0,%1,%2,%3}, {%4,%5,%6,%7}, {%8,%9}, {%0,%1,%2,%3};"
        : "+f"(c[0]), "+f"(c[1]), "+f"(c[2]), "+f"(c[3])
        : "r"(a0), "r"(a1), "r"(a2), "r"(a3), "r"(b0), "r"(b1));
}

// pair-interleave: rows (m, m+8) adjacent within each 16-row block
__device__ __forceinline__ int pair_idx(int m) {
    return ((m >> 4) << 4) + ((m & 7) << 1) + ((m >> 3) & 1);
}

#define TSTR 136   // [k][m] tile stride: conflict-free fragment LDS
#define VSTR 72    // V tile [t][d] stride

// proj: K-chunk 16, double-buffered -> half the smem of the old chunk-32
#define PKC 16
#define PBUF16 (PKC*TSTR)                 // 2176 words
#define MMA_SMEM_BYTES (4*PBUF16*4)       // 34,816 B -> 2 CTAs/SM

// fused kernel smem layout (words), t-tile = 128
#define FQ_OFF  0
#define FK_OFF  (64*TSTR)                 // 8704
#define FP_OFF  (FK_OFF + 64*TSTR)        // 17408
#define FV_OFF  (FP_OFF + 128*TSTR)       // 34816
#define FR_OFF  (FV_OFF + 128*VSTR)       // 44032
#define FUSED_SMEM_BYTES ((FR_OFF + 128) * 4)   // 176,640 B

// ---------------------------------------------------------------------------
// Kernel 1: projection via mma.sync tf32.
// 128x128 tile, K-chunk 16 (prefetch regs halved: pa[2]/pb[2]), pair-
// interleaved A with LDS.64 fragments, __launch_bounds__(256,2):
// ~120 natural regs -> capped 128 without spill -> 2 CTAs/SM.
// ---------------------------------------------------------------------------
__global__ __launch_bounds__(256, 2) void proj_mma_kernel(
    const float* __restrict__ X, const float* __restrict__ W,
    const float* __restrict__ bias, float* __restrict__ out)
{
    extern __shared__ uint32_t sm[];
    uint32_t* As = sm;
    uint32_t* Bs = sm + 2*PBUF16;

    const int tid  = threadIdx.x;
    const int warp = tid >> 5, lane = tid & 31;
    const int wm = warp & 1, wn = warp >> 1;
    const int n0 = blockIdx.x * 128, m0 = blockIdx.y * 128;
    const int lrow = tid >> 1;
    const int cq   = (tid & 1) * 8;     // k sub-offset 0/8 within 16-chunk
    const int pidx = pair_idx(lrow);

    const float* Xr = X + (size_t)(m0 + lrow) * 1024 + cq;
    const float* Wr = W + (size_t)(n0 + lrow) * 1024 + cq;

    float c[4][4][4];
#pragma unroll
    for (int mt = 0; mt < 4; mt++)
#pragma unroll
        for (int nt = 0; nt < 4; nt++)
#pragma unroll
            for (int e = 0; e < 4; e++) c[mt][nt][e] = 0.f;

    const int r  = lane >> 2;
    const int ci = lane & 3;

    float4 pa[2], pb[2];
#pragma unroll
    for (int j = 0; j < 2; j++) {
        pa[j] = *(const float4*)(Xr + 4 * j);
        pb[j] = *(const float4*)(Wr + 4 * j);
    }
    {
        uint32_t* da = As;
        uint32_t* db = Bs;
#pragma unroll
        for (int j = 0; j < 2; j++) {
            int k = cq + 4 * j;
            da[(k+0)*TSTR + pidx] = f2tf(pa[j].x);
            da[(k+1)*TSTR + pidx] = f2tf(pa[j].y);
            da[(k+2)*TSTR + pidx] = f2tf(pa[j].z);
            da[(k+3)*TSTR + pidx] = f2tf(pa[j].w);
            db[(k+0)*TSTR + lrow] = f2tf(pb[j].x);
            db[(k+1)*TSTR + lrow] = f2tf(pb[j].y);
            db[(k+2)*TSTR + lrow] = f2tf(pb[j].z);
            db[(k+3)*TSTR + lrow] = f2tf(pb[j].w);
        }
    }
    __syncthreads();

    for (int i = 0; i < 64; i++) {     // 64 chunks of 16
        if (i + 1 < 64) {
            const float* xr = Xr + (i + 1) * PKC;
            const float* wr = Wr + (i + 1) * PKC;
#pragma unroll
            for (int j = 0; j < 2; j++) {
                pa[j] = *(const float4*)(xr + 4 * j);
                pb[j] = *(const float4*)(wr + 4 * j);
            }
        }
        {
            uint32_t* Ab = As + (i & 1) * PBUF16 + wm * 64;
            uint32_t* Bb = Bs + (i & 1) * PBUF16 + wn * 32;
#pragma unroll
            for (int kf = 0; kf < PKC; kf += 8) {
                uint32_t a[4][4], b[4][2];
#pragma unroll
                for (int mt = 0; mt < 4; mt++) {
                    uint2 va0 = *(const uint2*)&Ab[(kf+ci  )*TSTR + mt*16 + r*2];
                    uint2 va1 = *(const uint2*)&Ab[(kf+4+ci)*TSTR + mt*16 + r*2];
                    a[mt][0] = va0.x;  a[mt][1] = va0.y;
                    a[mt][2] = va1.x;  a[mt][3] = va1.y;
                }
#pragma unroll
                for (int nt = 0; nt < 4; nt++) {
                    b[nt][0] = Bb[(kf+ci  )*TSTR + nt*8 + r];
                    b[nt][1] = Bb[(kf+4+ci)*TSTR + nt*8 + r];
                }
#pragma unroll
                for (int mt = 0; mt < 4; mt++)
#pragma unroll
                    for (int nt = 0; nt < 4; nt++)
                        mma_tf32(c[mt][nt], a[mt][0], a[mt][1], a[mt][2], a[mt][3],
                                 b[nt][0], b[nt][1]);
            }
        }
        if (i + 1 < 64) {
            uint32_t* da = As + ((i + 1) & 1) * PBUF16;
            uint32_t* db = Bs + ((i + 1) & 1) * PBUF16;
#pragma unroll
            for (int j = 0; j < 2; j++) {
                int k = cq + 4 * j;
                da[(k+0)*TSTR + pidx] = f2tf(pa[j].x);
                da[(k+1)*TSTR + pidx] = f2tf(pa[j].y);
                da[(k+2)*TSTR + pidx] = f2tf(pa[j].z);
                da[(k+3)*TSTR + pidx] = f2tf(pa[j].w);
                db[(k+0)*TSTR + lrow] = f2tf(pb[j].x);
                db[(k+1)*TSTR + lrow] = f2tf(pb[j].y);
                db[(k+2)*TSTR + lrow] = f2tf(pb[j].z);
                db[(k+3)*TSTR + lrow] = f2tf(pb[j].w);
            }
            __syncthreads();
        }
    }

    const int nb   = n0 + wn * 32;
    const int head = nb >> 6;
    const int d0   = nb & 63;
#pragma unroll
    for (int mt = 0; mt < 4; mt++) {
        int m = m0 + wm * 64 + mt * 16 + r;
        int bidx = m >> 10, s = m & 1023;
        float* po = out + (((size_t)(bidx * NHH + head)) * SS + s) * HDD + d0;
#pragma unroll
        for (int nt = 0; nt < 4; nt++) {
            int dn = nt * 8 + ci * 2;
            float2 bb = *(const float2*)&bias[nb + dn];
            float2 o0, o1;
            o0.x = c[mt][nt][0] + bb.x;  o0.y = c[mt][nt][1] + bb.y;
            o1.x = c[mt][nt][2] + bb.x;  o1.y = c[mt][nt][3] + bb.y;
            *(float2*)&po[dn]          = o0;
            *(float2*)&po[dn + 8*HDD]  = o1;
        }
    }
}

// ---------------------------------------------------------------------------
// Kernel 2 (fused): scores + softmax (no max-sub) + P@V, t-tile = 128,
// 512 threads, pair-interleaved Qs/Ps (LDS.64/STS.64) — round-16 best
// (296us), unchanged.
// ---------------------------------------------------------------------------
__global__ __launch_bounds__(512) void fused_attn_kernel(
    const float* __restrict__ Q, const float* __restrict__ K,
    const float* __restrict__ V, const int* __restrict__ mask,
    float* __restrict__ scores, float* __restrict__ ctx)
{
    extern __shared__ uint32_t sm[];
    uint32_t* Qs = sm + FQ_OFF;    // [64 d][TSTR] tf32, s pair-interleaved
    uint32_t* Ks = sm + FK_OFF;    // [64 d][TSTR]
    uint32_t* Ps = sm + FP_OFF;    // [128 t][TSTR] exp tf32, s pair-interleaved
    uint32_t* Vs = sm + FV_OFF;    // [128 t][VSTR]
    float*    Rs = (float*)(sm + FR_OFF);   // [128] row sums

    const int tid  = threadIdx.x;
    const int warp = tid >> 5, lane = tid & 31;
    const int r  = lane >> 2;
    const int ci = lane & 3;
    const int bh = blockIdx.y;
    const int s0 = blockIdx.x * 128;

    const float* Qb = Q + (size_t)bh * SS * HDD;
    const float* Kb = K + (size_t)bh * SS * HDD;
    const float* Vb = V + (size_t)bh * SS * HDD;

    const int lrow = tid >> 2;          // 0..127
    const int cq   = (tid & 3) * 16;    // d quarter
    const int plrow = pair_idx(lrow);   // pair-interleaved s index

    if (tid < 128) Rs[tid] = 0.f;

    // load Q tile (once): Qs[d][pidx(s)], 4 float4 per thread
    {
        const float* qr = Qb + (size_t)(s0 + lrow) * HDD + cq;
#pragma unroll
        for (int j = 0; j < 4; j++) {
            float4 v = *(const float4*)(qr + 4 * j);
            int k = cq + 4 * j;
            Qs[(k+0)*TSTR + plrow] = f2tf(v.x);
            Qs[(k+1)*TSTR + plrow] = f2tf(v.y);
            Qs[(k+2)*TSTR + plrow] = f2tf(v.z);
            Qs[(k+3)*TSTR + plrow] = f2tf(v.w);
        }
    }

    const int wm = warp & 3, wn = warp >> 2;   // S: 32s x 32t | PV: 32s x 16d

    float o[2][2][4];
#pragma unroll
    for (int mt = 0; mt < 2; mt++)
#pragma unroll
        for (int nt = 0; nt < 2; nt++)
#pragma unroll
            for (int e = 0; e < 4; e++) o[mt][nt][e] = 0.f;

    for (int tt = 0; tt < 8; tt++) {
        const int t0 = tt * 128;
        __syncthreads();   // Ks/Vs/Ps reuse barrier (also orders Rs zeroing)
        // load K,V tiles (rows t0..t0+127), 4 float4 each per thread
        {
            const float* kr = Kb + (size_t)(t0 + lrow) * HDD + cq;
            const float* vr = Vb + (size_t)(t0 + lrow) * HDD + cq;
#pragma unroll
            for (int j = 0; j < 4; j++) {
                float4 kv = *(const float4*)(kr + 4 * j);
                float4 vv = *(const float4*)(vr + 4 * j);
                int k = cq + 4 * j;
                Ks[(k+0)*TSTR + lrow] = f2tf(kv.x);
                Ks[(k+1)*TSTR + lrow] = f2tf(kv.y);
                Ks[(k+2)*TSTR + lrow] = f2tf(kv.z);
                Ks[(k+3)*TSTR + lrow] = f2tf(kv.w);
                Vs[lrow*VSTR + k+0] = f2tf(vv.x);
                Vs[lrow*VSTR + k+1] = f2tf(vv.y);
                Vs[lrow*VSTR + k+2] = f2tf(vv.z);
                Vs[lrow*VSTR + k+3] = f2tf(vv.w);
            }
        }
        __syncthreads();

        // ---- prefetch mask tile into registers (consumed after S-MMA) ----
        int2 mk0[2][4], mk1[2][4];
#pragma unroll
        for (int mt = 0; mt < 2; mt++) {
            int s = wm * 32 + mt * 16 + r;
            size_t rowoff = ((size_t)bh * SS + (s0 + s)) * SS;
#pragma unroll
            for (int nt = 0; nt < 4; nt++) {
                int lt = wn * 32 + nt * 8 + ci * 2;
                size_t off0 = rowoff + t0 + lt;
                mk0[mt][nt] = *(const int2*)&mask[off0];
                mk1[mt][nt] = *(const int2*)&mask[off0 + 8 * SS];
            }
        }

        // ---- S = Q K^T for this tile (warp: 32s x 32t), LDS.64 A-frags ----
        float c[2][4][4];
#pragma unroll
        for (int mt = 0; mt < 2; mt++)
#pragma unroll
            for (int nt = 0; nt < 4; nt++)
#pragma unroll
                for (int e = 0; e < 4; e++) c[mt][nt][e] = 0.f;

        uint32_t* Ab = Qs + wm * 32;
        uint32_t* Bb = Ks + wn * 32;
#pragma unroll
        for (int kf = 0; kf < 64; kf += 8) {
            uint32_t a[2][4], b[4][2];
#pragma unroll
            for (int mt = 0; mt < 2; mt++) {
                uint2 va0 = *(const uint2*)&Ab[(kf+ci  )*TSTR + mt*16 + r*2];
                uint2 va1 = *(const uint2*)&Ab[(kf+4+ci)*TSTR + mt*16 + r*2];
                a[mt][0] = va0.x;  a[mt][1] = va0.y;
                a[mt][2] = va1.x;  a[mt][3] = va1.y;
            }
#pragma unroll
            for (int nt = 0; nt < 4; nt++) {
                b[nt][0] = Bb[(kf+ci  )*TSTR + nt*8 + r];
                b[nt][1] = Bb[(kf+4+ci)*TSTR + nt*8 + r];
            }
#pragma unroll
            for (int mt = 0; mt < 2; mt++)
#pragma unroll
                for (int nt = 0; nt < 4; nt++)
                    mma_tf32(c[mt][nt], a[mt][0], a[mt][1], a[mt][2], a[mt][3],
                             b[nt][0], b[nt][1]);
        }

        // ---- epilogue: mask+scale, write scores, exp -> Ps (STS.64) ----
#pragma unroll
        for (int mt = 0; mt < 2; mt++) {
            int s = wm * 32 + mt * 16 + r;
            int pbase = ((s >> 4) << 4) + r * 2;   // pidx(s); pidx(s+8)=pbase+1
            size_t rowoff = ((size_t)bh * SS + (s0 + s)) * SS;
            float rsa = 0.f, rsb = 0.f;   // rows s and s+8
#pragma unroll
            for (int nt = 0; nt < 4; nt++) {
                int lt = wn * 32 + nt * 8 + ci * 2;
                size_t off0 = rowoff + t0 + lt;
                size_t off1 = off0 + 8 * SS;
                float2 sv0, sv1;
                sv0.x = c[mt][nt][0] * 0.125f + (mk0[mt][nt].x != 0 ? -9999.f : 0.f);
                sv0.y = c[mt][nt][1] * 0.125f + (mk0[mt][nt].y != 0 ? -9999.f : 0.f);
                sv1.x = c[mt][nt][2] * 0.125f + (mk1[mt][nt].x != 0 ? -9999.f : 0.f);
                sv1.y = c[mt][nt][3] * 0.125f + (mk1[mt][nt].y != 0 ? -9999.f : 0.f);
                *(float2*)&scores[off0] = sv0;
                *(float2*)&scores[off1] = sv1;
                uint32_t p0 = f2tf(__expf(sv0.x));
                uint32_t p1 = f2tf(__expf(sv0.y));
                uint32_t p2 = f2tf(__expf(sv1.x));
                uint32_t p3 = f2tf(__expf(sv1.y));
                uint2 w02 = make_uint2(p0, p2);   // rows (s, s+8) at col lt
                uint2 w13 = make_uint2(p1, p3);   // rows (s, s+8) at col lt+1
                *(uint2*)&Ps[(lt  )*TSTR + pbase] = w02;
                *(uint2*)&Ps[(lt+1)*TSTR + pbase] = w13;
                rsa += __uint_as_float(p0) + __uint_as_float(p1);
                rsb += __uint_as_float(p2) + __uint_as_float(p3);
            }
            rsa += __shfl_xor_sync(0xffffffffu, rsa, 1);
            rsa += __shfl_xor_sync(0xffffffffu, rsa, 2);
            rsb += __shfl_xor_sync(0xffffffffu, rsb, 1);
            rsb += __shfl_xor_sync(0xffffffffu, rsb, 2);
            if (ci == 0) {
                atomicAdd(&Rs[s], rsa);
                atomicAdd(&Rs[s + 8], rsb);
            }
        }
        __syncthreads();   // Ps visible

        // ---- PV accumulate (LDS.64 A-frags): o += P @ V ----
        {
            uint32_t* Pb = Ps + wm * 32;
            uint32_t* Vbk = Vs + wn * 16;
#pragma unroll
            for (int kf = 0; kf < 128; kf += 8) {
                uint32_t a[2][4], b[2][2];
#pragma unroll
                for (int mt = 0; mt < 2; mt++) {
                    uint2 va0 = *(const uint2*)&Pb[(kf+ci  )*TSTR + mt*16 + r*2];
                    uint2 va1 = *(const uint2*)&Pb[(kf+4+ci)*TSTR + mt*16 + r*2];
                    a[mt][0] = va0.x;  a[mt][1] = va0.y;
                    a[mt][2] = va1.x;  a[mt][3] = va1.y;
                }
#pragma unroll
                for (int nt = 0; nt < 2; nt++) {
                    b[nt][0] = Vbk[(kf+ci  )*VSTR + nt*8 + r];
                    b[nt][1] = Vbk[(kf+4+ci)*VSTR + nt*8 + r];
                }
#pragma unroll
                for (int mt = 0; mt < 2; mt++)
#pragma unroll
                    for (int nt = 0; nt < 2; nt++)
                        mma_tf32(o[mt][nt], a[mt][0], a[mt][1], a[mt][2], a[mt][3],
                                 b[nt][0], b[nt][1]);
            }
        }
    }

    __syncthreads();

    // final: normalize, write ctx [b][s][h*64+d]
    const int bidx = bh >> 4;
    const int h = bh & 15;
#pragma unroll
    for (int mt = 0; mt < 2; mt++) {
        int s = wm * 32 + mt * 16 + r;
        float inv0 = 1.f / Rs[s];
        float inv1 = 1.f / Rs[s + 8];
        float* po0 = ctx + ((size_t)bidx * SS + (s0 + s)) * HH + h * HDD;
        float* po1 = po0 + 8 * HH;
#pragma unroll
        for (int nt = 0; nt < 2; nt++) {
            int d = wn * 16 + nt * 8 + ci * 2;
            float2 w0, w1;
            w0.x = o[mt][nt][0] * inv0;  w0.y = o[mt][nt][1] * inv0;
            w1.x = o[mt][nt][2] * inv1;  w1.y = o[mt][nt][3] * inv1;
            *(float2*)&po0[d] = w0;
            *(float2*)&po1[d] = w1;
        }
    }
}

// ---------------------------------------------------------------------------
extern "C" void kernel_launch(void* const* d_in, const int* in_sizes, int n_in,
                              void* d_out, int out_size) {
    const float* qx = (const float*)d_in[0];
    const float* kx = (const float*)d_in[1];
    const float* vx = (const float*)d_in[2];
    const int* mask = (const int*)d_in[3];
    const float* Wq = (const float*)d_in[4];
    const float* bq = (const float*)d_in[5];
    const float* Wk = (const float*)d_in[6];
    const float* bk = (const float*)d_in[7];
    const float* Wv = (const float*)d_in[8];
    const float* bv = (const float*)d_in[9];

    float *qp, *kp, *vp, *sfb, *cfb;
    cudaGetSymbolAddress((void**)&qp, g_q);
    cudaGetSymbolAddress((void**)&kp, g_k);
    cudaGetSymbolAddress((void**)&vp, g_v);
    cudaGetSymbolAddress((void**)&sfb, g_scores_fb);
    cudaGetSymbolAddress((void**)&cfb, g_ctx_fb);

    float* ctx_out;
    float* scores_out;
    if (out_size >= CTX_ELEMS + SCORES_ELEMS) {
        ctx_out = (float*)d_out;
        scores_out = (float*)d_out + CTX_ELEMS;
    } else if (out_size == SCORES_ELEMS) {
        scores_out = (float*)d_out;
        ctx_out = cfb;
    } else {
        ctx_out = (float*)d_out;
        scores_out = sfb;
    }

    cudaFuncSetAttribute(proj_mma_kernel,
                         cudaFuncAttributeMaxDynamicSharedMemorySize, MMA_SMEM_BYTES);
    cudaFuncSetAttribute(fused_attn_kernel,
                         cudaFuncAttributeMaxDynamicSharedMemorySize, FUSED_SMEM_BYTES);

    dim3 pg(8, 32);  // N/128, M/128
    proj_mma_kernel<<<pg, 256, MMA_SMEM_BYTES>>>(qx, Wq, bq, qp);
    proj_mma_kernel<<<pg, 256, MMA_SMEM_BYTES>>>(kx, Wk, bk, kp);
    proj_mma_kernel<<<pg, 256, MMA_SMEM_BYTES>>>(vx, Wv, bv, vp);
    fused_attn_kernel<<<dim3(8, BH), 512, FUSED_SMEM_BYTES>>>(
        qp, kp, vp, mask, scores_out, ctx_out);
}